// round 6
// baseline (speedup 1.0000x reference)
#include <cuda_runtime.h>
#include <math.h>

#define F    64      // input / hidden features
#define CC   40      // classes
#define NMAX 100000
#define EMAX 1600000

// ---------------- scratch (device globals: no allocs allowed) ----------------
__device__ int   g_is64;                // 1 if edge_index is int64, 0 if int32
__device__ int   g_cnt [NMAX];          // in-degree (excl self-loop)
__device__ int   g_off [NMAX];          // CSR row offsets (exclusive scan)
__device__ int   g_cur [NMAX];          // fill cursors (init = off)
__device__ int   g_src [EMAX];          // int-converted edge sources
__device__ int   g_dst [EMAX];          // int-converted edge dests
__device__ int   g_adj [EMAX];          // dst-grouped source lists
__device__ float g_dinv[NMAX];
__device__ __align__(16) float g_hs [(size_t)NMAX * F];   // dinv-scaled x@W1
__device__ __align__(16) float g_h1 [(size_t)NMAX * F];   // relu(layer-1 out)
__device__ __align__(16) float g_hs2[(size_t)NMAX * CC];  // dinv-scaled h1@W2

// ---------------- dtype detection ----------------
// int64 edges with values in [0, 2^31): every odd 32-bit word is 0.
// For int32 random edge data, 64 consecutive odd words all being 0 is impossible.
__global__ void k_detect(const int* __restrict__ ei32) {
    if (threadIdx.x == 0) {
        int all0 = 1;
        for (int i = 1; i < 128; i += 2) all0 &= (ei32[i] == 0);
        g_is64 = all0;
    }
}

// ---------------- CSR build (int atomics only) ----------------
__global__ void k_zero(int n) {
    int i = blockIdx.x * blockDim.x + threadIdx.x;
    if (i < n) g_cnt[i] = 0;
}

// convert edges -> int (clamped) and count in-degrees; handles both dtypes
__global__ void k_conv(const void* __restrict__ ei, int E, int n) {
    int e = blockIdx.x * blockDim.x + threadIdx.x;
    if (e >= E) return;
    int s, d;
    if (g_is64) {
        const long long* p = (const long long*)ei;
        s = (int)p[e];
        d = (int)p[(size_t)E + e];
    } else {
        const int* p = (const int*)ei;
        s = p[e];
        d = p[(size_t)E + e];
    }
    s = min(max(s, 0), n - 1);
    d = min(max(d, 0), n - 1);
    g_src[e] = s;
    g_dst[e] = d;
    atomicAdd(&g_cnt[d], 1);
}

// single-block exclusive scan of g_cnt -> g_off, g_cur; also dinv = rsqrt(cnt+1)
__global__ void k_scan(int n) {
    __shared__ int wsum[32];
    __shared__ int carry_s;
    int tid = threadIdx.x, lane = tid & 31, wid = tid >> 5;
    if (tid == 0) carry_s = 0;
    __syncthreads();

    for (int base = 0; base < n; base += 1024) {
        int i = base + tid;
        int v = (i < n) ? g_cnt[i] : 0;
        int x = v;
#pragma unroll
        for (int off = 1; off < 32; off <<= 1) {
            int t = __shfl_up_sync(0xFFFFFFFFu, x, off);
            if (lane >= off) x += t;
        }
        if (lane == 31) wsum[wid] = x;      // warp totals
        __syncthreads();
        if (wid == 0) {
            int w = wsum[lane];
#pragma unroll
            for (int off = 1; off < 32; off <<= 1) {
                int t = __shfl_up_sync(0xFFFFFFFFu, w, off);
                if (lane >= off) w += t;
            }
            wsum[lane] = w;                 // inclusive scan of warp totals
        }
        __syncthreads();
        int carry = carry_s;
        int wbase = (wid == 0) ? 0 : wsum[wid - 1];
        if (i < n) {
            int excl = carry + wbase + x - v;
            g_off[i] = excl;
            g_cur[i] = excl;
            g_dinv[i] = rsqrtf((float)(v + 1));   // +1 self-loop
        }
        __syncthreads();                    // everyone done reading carry_s/wsum
        if (tid == 1023) carry_s = carry + wsum[31];
        __syncthreads();
    }
}

__global__ void k_fill(int E) {
    int e = blockIdx.x * blockDim.x + threadIdx.x;
    if (e >= E) return;
    int s = g_src[e];
    int d = g_dst[e];
    int pos = atomicAdd(&g_cur[d], 1);
    pos = min(max(pos, 0), E - 1);
    g_adj[pos] = s;
}

// ---------------- GEMM1: g_hs = (x @ W1) * dinv[row] ----------------
__global__ void k_gemm1(const float* __restrict__ x, const float* __restrict__ W, int n) {
    __shared__ float sW[F * F];
    __shared__ float sX[64 * F];
    int tid  = threadIdx.x;
    int row0 = blockIdx.x * 64;

    for (int i = tid; i < F * F; i += 256) sW[i] = W[i];
    for (int i = tid; i < 64 * F; i += 256) {
        int r = row0 + (i >> 6);
        sX[i] = (r < n) ? x[(size_t)r * F + (i & 63)] : 0.0f;
    }
    __syncthreads();

    int col = tid & 63;
    int rg  = tid >> 6;
    float a[16];
#pragma unroll
    for (int j = 0; j < 16; j++) a[j] = 0.0f;

    for (int k = 0; k < F; k++) {
        float w = sW[k * F + col];
#pragma unroll
        for (int j = 0; j < 16; j++)
            a[j] = fmaf(sX[(rg * 16 + j) * F + k], w, a[j]);
    }

#pragma unroll
    for (int j = 0; j < 16; j++) {
        int r = row0 + rg * 16 + j;
        if (r < n) g_hs[(size_t)r * F + col] = a[j] * g_dinv[r];
    }
}

// ------- gather layer 1 (fused agg + bias + relu): warp per dst row ----------
__global__ void k_gather1(const float* __restrict__ b1, int n, int E) {
    int warp = (blockIdx.x * 256 + threadIdx.x) >> 5;
    int lane = threadIdx.x & 31;
    if (warp >= n) return;
    int d = warp;

    float2 acc = ((const float2*)(g_hs + (size_t)d * F))[lane];  // self-loop
    int beg = min(max(g_off[d], 0), E);
    int end = min(beg + g_cnt[d], E);
    int j = beg;
    for (; j + 4 <= end; j += 4) {
        int s0 = g_adj[j], s1 = g_adj[j+1], s2 = g_adj[j+2], s3 = g_adj[j+3];
        float2 v0 = ((const float2*)(g_hs + (size_t)s0 * F))[lane];
        float2 v1 = ((const float2*)(g_hs + (size_t)s1 * F))[lane];
        float2 v2 = ((const float2*)(g_hs + (size_t)s2 * F))[lane];
        float2 v3 = ((const float2*)(g_hs + (size_t)s3 * F))[lane];
        acc.x += (v0.x + v1.x) + (v2.x + v3.x);
        acc.y += (v0.y + v1.y) + (v2.y + v3.y);
    }
    for (; j < end; j++) {
        float2 v = ((const float2*)(g_hs + (size_t)g_adj[j] * F))[lane];
        acc.x += v.x; acc.y += v.y;
    }

    float di = g_dinv[d];
    float2 o;
    o.x = fmaxf(fmaf(di, acc.x, b1[2 * lane]),     0.0f);
    o.y = fmaxf(fmaf(di, acc.y, b1[2 * lane + 1]), 0.0f);
    ((float2*)(g_h1 + (size_t)d * F))[lane] = o;
}

// ---------------- GEMM2: g_hs2 = (h1 @ W2) * dinv[row] ----------------
__global__ void k_gemm2(const float* __restrict__ W, int n) {
    __shared__ float sW[F * CC];
    __shared__ float sH[64 * F];
    int tid  = threadIdx.x;            // 320
    int row0 = blockIdx.x * 64;

    for (int i = tid; i < F * CC; i += 320) sW[i] = W[i];
    for (int i = tid; i < 64 * F; i += 320) {
        int r = row0 + (i >> 6);
        sH[i] = (r < n) ? g_h1[(size_t)r * F + (i & 63)] : 0.0f;
    }
    __syncthreads();

    int col = tid % 40;
    int rg  = tid / 40;
    float a[8];
#pragma unroll
    for (int j = 0; j < 8; j++) a[j] = 0.0f;

    for (int k = 0; k < F; k++) {
        float w = sW[k * CC + col];
#pragma unroll
        for (int j = 0; j < 8; j++)
            a[j] = fmaf(sH[(rg * 8 + j) * F + k], w, a[j]);
    }

#pragma unroll
    for (int j = 0; j < 8; j++) {
        int r = row0 + rg * 8 + j;
        if (r < n) g_hs2[(size_t)r * CC + col] = a[j] * g_dinv[r];
    }
}

// ------- gather layer 2 (fused agg + bias + log_softmax): warp per dst -------
__global__ void k_gather2(const float* __restrict__ b2, float* __restrict__ out,
                          int n, int E) {
    int warp = (blockIdx.x * 256 + threadIdx.x) >> 5;
    int lane = threadIdx.x & 31;
    if (warp >= n) return;
    int d = warp;
    bool act = (lane < 20);   // 20 lanes x float2 = 40 cols

    float2 acc = act ? ((const float2*)(g_hs2 + (size_t)d * CC))[lane]
                     : make_float2(0.0f, 0.0f);
    int beg = min(max(g_off[d], 0), E);
    int end = min(beg + g_cnt[d], E);
    int j = beg;
    for (; j + 4 <= end; j += 4) {
        int s0 = g_adj[j], s1 = g_adj[j+1], s2 = g_adj[j+2], s3 = g_adj[j+3];
        if (act) {
            float2 v0 = ((const float2*)(g_hs2 + (size_t)s0 * CC))[lane];
            float2 v1 = ((const float2*)(g_hs2 + (size_t)s1 * CC))[lane];
            float2 v2 = ((const float2*)(g_hs2 + (size_t)s2 * CC))[lane];
            float2 v3 = ((const float2*)(g_hs2 + (size_t)s3 * CC))[lane];
            acc.x += (v0.x + v1.x) + (v2.x + v3.x);
            acc.y += (v0.y + v1.y) + (v2.y + v3.y);
        }
    }
    for (; j < end; j++) {
        int s = g_adj[j];
        if (act) {
            float2 v = ((const float2*)(g_hs2 + (size_t)s * CC))[lane];
            acc.x += v.x; acc.y += v.y;
        }
    }

    float di = g_dinv[d];
    float vx = act ? fmaf(di, acc.x, b2[2 * lane])     : -INFINITY;
    float vy = act ? fmaf(di, acc.y, b2[2 * lane + 1]) : -INFINITY;

    float m = fmaxf(vx, vy);
#pragma unroll
    for (int off = 16; off; off >>= 1) m = fmaxf(m, __shfl_xor_sync(0xFFFFFFFFu, m, off));

    float s = act ? (expf(vx - m) + expf(vy - m)) : 0.0f;
#pragma unroll
    for (int off = 16; off; off >>= 1) s += __shfl_xor_sync(0xFFFFFFFFu, s, off);

    float lse = m + logf(s);
    if (act) {
        float2 o; o.x = vx - lse; o.y = vy - lse;
        ((float2*)(out + (size_t)d * CC))[lane] = o;
    }
}

// ---------------- launch ------------------------------------------------------
extern "C" void kernel_launch(void* const* d_in, const int* in_sizes, int n_in,
                              void* d_out, int out_size) {
    const float* x  = (const float*)d_in[0];
    const void*  ei = d_in[1];                 // int64 OR int32 [2, E] (detected)
    const float* W1 = (const float*)d_in[2];
    const float* b1 = (const float*)d_in[3];
    const float* W2 = (const float*)d_in[4];
    const float* b2 = (const float*)d_in[5];
    float* out = (float*)d_out;

    int n = in_sizes[0] / F;       // 100000
    int E = in_sizes[1] / 2;       // 1600000

    k_detect<<<1, 32>>>((const int*)ei);
    k_zero<<<(n + 255) / 256, 256>>>(n);
    k_conv<<<(E + 255) / 256, 256>>>(ei, E, n);
    k_scan<<<1, 1024>>>(n);
    k_fill<<<(E + 255) / 256, 256>>>(E);

    k_gemm1  <<<(n + 63) / 64, 256>>>(x, W1, n);
    k_gather1<<<(n * 32 + 255) / 256, 256>>>(b1, n, E);
    k_gemm2  <<<(n + 63) / 64, 320>>>(W2, n);
    k_gather2<<<(n * 32 + 255) / 256, 256>>>(b2, out, n, E);
}

// round 7
// speedup vs baseline: 1.9561x; 1.9561x over previous
#include <cuda_runtime.h>
#include <math.h>

#define F    64      // input / hidden features
#define CC   40      // classes
#define NMAX 100000
#define EMAX 1600000

// ---------------- scratch (device globals: no allocs allowed) ----------------
__device__ int   g_is64;                // 1 if edge_index is int64, 0 if int32
__device__ int   g_cnt [NMAX];          // in-degree (excl self-loop)
__device__ int   g_off [NMAX];          // CSR row offsets (exclusive scan)
__device__ int   g_cur [NMAX];          // fill cursors (init = off)
__device__ int   g_src [EMAX];          // int-converted edge sources
__device__ int   g_dst [EMAX];          // int-converted edge dests
__device__ int   g_adj [EMAX];          // dst-grouped source lists
__device__ int   g_bsum[128];           // scan block sums
__device__ int   g_boff[128];           // scanned block offsets
__device__ float g_dinv[NMAX];
__device__ __align__(16) float g_hs [(size_t)NMAX * F];   // dinv-scaled x@W1
__device__ __align__(16) float g_h1 [(size_t)NMAX * F];   // relu(layer-1 out)
__device__ __align__(16) float g_hs2[(size_t)NMAX * CC];  // dinv-scaled h1@W2

// ---------------- dtype detection ----------------
// int64 edges with values in [0, 2^31): every odd 32-bit word is 0.
__global__ void k_detect(const int* __restrict__ ei32) {
    if (threadIdx.x == 0) {
        int all0 = 1;
        for (int i = 1; i < 128; i += 2) all0 &= (ei32[i] == 0);
        g_is64 = all0;
    }
}

// ---------------- CSR build (int atomics only) ----------------
__global__ void k_zero(int n) {
    int i = blockIdx.x * blockDim.x + threadIdx.x;
    if (i < n) g_cnt[i] = 0;
}

// convert edges -> int (clamped) and count in-degrees; handles both dtypes
__global__ void k_conv(const void* __restrict__ ei, int E, int n) {
    int e = blockIdx.x * blockDim.x + threadIdx.x;
    if (e >= E) return;
    int s, d;
    if (g_is64) {
        const long long* p = (const long long*)ei;
        s = (int)p[e];
        d = (int)p[(size_t)E + e];
    } else {
        const int* p = (const int*)ei;
        s = p[e];
        d = p[(size_t)E + e];
    }
    s = min(max(s, 0), n - 1);
    d = min(max(d, 0), n - 1);
    g_src[e] = s;
    g_dst[e] = d;
    atomicAdd(&g_cnt[d], 1);
}

// -------- multi-block exclusive scan of g_cnt -> g_off/g_cur ------------------
// phase 1: per-block (1024) scan; write block-local exclusive + block sums + dinv
__global__ void k_scan1(int n) {
    __shared__ int wsum[32];
    int tid = threadIdx.x, lane = tid & 31, wid = tid >> 5;
    int i = blockIdx.x * 1024 + tid;
    int v = (i < n) ? g_cnt[i] : 0;
    int x = v;
#pragma unroll
    for (int off = 1; off < 32; off <<= 1) {
        int t = __shfl_up_sync(0xFFFFFFFFu, x, off);
        if (lane >= off) x += t;
    }
    if (lane == 31) wsum[wid] = x;
    __syncthreads();
    if (wid == 0) {
        int w = wsum[lane];
#pragma unroll
        for (int off = 1; off < 32; off <<= 1) {
            int t = __shfl_up_sync(0xFFFFFFFFu, w, off);
            if (lane >= off) w += t;
        }
        wsum[lane] = w;                 // inclusive scan of warp totals
    }
    __syncthreads();
    int wbase = (wid == 0) ? 0 : wsum[wid - 1];
    if (i < n) {
        g_off[i]  = wbase + x - v;      // block-local exclusive
        g_dinv[i] = rsqrtf((float)(v + 1));   // +1 self-loop
    }
    if (tid == 1023) g_bsum[blockIdx.x] = wbase + x;   // block total
}

// phase 2: one block of 128 threads scans the (<=128) block sums -> g_boff
__global__ void k_scan2(int nb) {
    __shared__ int wsum[4];
    int tid = threadIdx.x, lane = tid & 31, wid = tid >> 5;
    int v = (tid < nb) ? g_bsum[tid] : 0;
    int x = v;
#pragma unroll
    for (int off = 1; off < 32; off <<= 1) {
        int t = __shfl_up_sync(0xFFFFFFFFu, x, off);
        if (lane >= off) x += t;
    }
    if (lane == 31) wsum[wid] = x;
    __syncthreads();
    if (tid == 0) {
        int c = 0;
#pragma unroll
        for (int w = 0; w < 4; w++) { int t = wsum[w]; wsum[w] = c; c += t; }
    }
    __syncthreads();
    g_boff[tid] = wsum[wid] + x - v;    // exclusive
}

// phase 3: add block offsets; init cursors
__global__ void k_scan3(int n) {
    int i = blockIdx.x * blockDim.x + threadIdx.x;
    if (i < n) {
        int o = g_off[i] + g_boff[i >> 10];
        g_off[i] = o;
        g_cur[i] = o;
    }
}

__global__ void k_fill(int E) {
    int e = blockIdx.x * blockDim.x + threadIdx.x;
    if (e >= E) return;
    int s = g_src[e];
    int d = g_dst[e];
    int pos = atomicAdd(&g_cur[d], 1);
    pos = min(max(pos, 0), E - 1);
    g_adj[pos] = s;
}

// ---------------- GEMM1: g_hs = (x @ W1) * dinv[row] ----------------
__global__ void k_gemm1(const float* __restrict__ x, const float* __restrict__ W, int n) {
    __shared__ float sW[F * F];
    __shared__ float sX[64 * F];
    int tid  = threadIdx.x;
    int row0 = blockIdx.x * 64;

    for (int i = tid; i < F * F; i += 256) sW[i] = W[i];
    for (int i = tid; i < 64 * F; i += 256) {
        int r = row0 + (i >> 6);
        sX[i] = (r < n) ? x[(size_t)r * F + (i & 63)] : 0.0f;
    }
    __syncthreads();

    int col = tid & 63;
    int rg  = tid >> 6;
    float a[16];
#pragma unroll
    for (int j = 0; j < 16; j++) a[j] = 0.0f;

    for (int k = 0; k < F; k++) {
        float w = sW[k * F + col];
#pragma unroll
        for (int j = 0; j < 16; j++)
            a[j] = fmaf(sX[(rg * 16 + j) * F + k], w, a[j]);
    }

#pragma unroll
    for (int j = 0; j < 16; j++) {
        int r = row0 + rg * 16 + j;
        if (r < n) g_hs[(size_t)r * F + col] = a[j] * g_dinv[r];
    }
}

// ------- gather layer 1 (fused agg + bias + relu): warp per dst row ----------
__global__ void k_gather1(const float* __restrict__ b1, int n, int E) {
    int warp = (blockIdx.x * 256 + threadIdx.x) >> 5;
    int lane = threadIdx.x & 31;
    if (warp >= n) return;
    int d = warp;

    float2 acc = ((const float2*)(g_hs + (size_t)d * F))[lane];  // self-loop
    int beg = min(max(g_off[d], 0), E);
    int end = min(beg + g_cnt[d], E);
    int j = beg;
    for (; j + 4 <= end; j += 4) {
        int s0 = g_adj[j], s1 = g_adj[j+1], s2 = g_adj[j+2], s3 = g_adj[j+3];
        float2 v0 = ((const float2*)(g_hs + (size_t)s0 * F))[lane];
        float2 v1 = ((const float2*)(g_hs + (size_t)s1 * F))[lane];
        float2 v2 = ((const float2*)(g_hs + (size_t)s2 * F))[lane];
        float2 v3 = ((const float2*)(g_hs + (size_t)s3 * F))[lane];
        acc.x += (v0.x + v1.x) + (v2.x + v3.x);
        acc.y += (v0.y + v1.y) + (v2.y + v3.y);
    }
    for (; j < end; j++) {
        float2 v = ((const float2*)(g_hs + (size_t)g_adj[j] * F))[lane];
        acc.x += v.x; acc.y += v.y;
    }

    float di = g_dinv[d];
    float2 o;
    o.x = fmaxf(fmaf(di, acc.x, b1[2 * lane]),     0.0f);
    o.y = fmaxf(fmaf(di, acc.y, b1[2 * lane + 1]), 0.0f);
    ((float2*)(g_h1 + (size_t)d * F))[lane] = o;
}

// ---------------- GEMM2: g_hs2 = (h1 @ W2) * dinv[row] ----------------
__global__ void k_gemm2(const float* __restrict__ W, int n) {
    __shared__ float sW[F * CC];
    __shared__ float sH[64 * F];
    int tid  = threadIdx.x;            // 320
    int row0 = blockIdx.x * 64;

    for (int i = tid; i < F * CC; i += 320) sW[i] = W[i];
    for (int i = tid; i < 64 * F; i += 320) {
        int r = row0 + (i >> 6);
        sH[i] = (r < n) ? g_h1[(size_t)r * F + (i & 63)] : 0.0f;
    }
    __syncthreads();

    int col = tid % 40;
    int rg  = tid / 40;
    float a[8];
#pragma unroll
    for (int j = 0; j < 8; j++) a[j] = 0.0f;

    for (int k = 0; k < F; k++) {
        float w = sW[k * CC + col];
#pragma unroll
        for (int j = 0; j < 8; j++)
            a[j] = fmaf(sH[(rg * 8 + j) * F + k], w, a[j]);
    }

#pragma unroll
    for (int j = 0; j < 8; j++) {
        int r = row0 + rg * 8 + j;
        if (r < n) g_hs2[(size_t)r * CC + col] = a[j] * g_dinv[r];
    }
}

// ------- gather layer 2 (fused agg + bias + log_softmax): warp per dst -------
__global__ void k_gather2(const float* __restrict__ b2, float* __restrict__ out,
                          int n, int E) {
    int warp = (blockIdx.x * 256 + threadIdx.x) >> 5;
    int lane = threadIdx.x & 31;
    if (warp >= n) return;
    int d = warp;
    bool act = (lane < 20);   // 20 lanes x float2 = 40 cols

    float2 acc = act ? ((const float2*)(g_hs2 + (size_t)d * CC))[lane]
                     : make_float2(0.0f, 0.0f);
    int beg = min(max(g_off[d], 0), E);
    int end = min(beg + g_cnt[d], E);
    int j = beg;
    for (; j + 4 <= end; j += 4) {
        int s0 = g_adj[j], s1 = g_adj[j+1], s2 = g_adj[j+2], s3 = g_adj[j+3];
        if (act) {
            float2 v0 = ((const float2*)(g_hs2 + (size_t)s0 * CC))[lane];
            float2 v1 = ((const float2*)(g_hs2 + (size_t)s1 * CC))[lane];
            float2 v2 = ((const float2*)(g_hs2 + (size_t)s2 * CC))[lane];
            float2 v3 = ((const float2*)(g_hs2 + (size_t)s3 * CC))[lane];
            acc.x += (v0.x + v1.x) + (v2.x + v3.x);
            acc.y += (v0.y + v1.y) + (v2.y + v3.y);
        }
    }
    for (; j < end; j++) {
        int s = g_adj[j];
        if (act) {
            float2 v = ((const float2*)(g_hs2 + (size_t)s * CC))[lane];
            acc.x += v.x; acc.y += v.y;
        }
    }

    float di = g_dinv[d];
    float vx = act ? fmaf(di, acc.x, b2[2 * lane])     : -INFINITY;
    float vy = act ? fmaf(di, acc.y, b2[2 * lane + 1]) : -INFINITY;

    float m = fmaxf(vx, vy);
#pragma unroll
    for (int off = 16; off; off >>= 1) m = fmaxf(m, __shfl_xor_sync(0xFFFFFFFFu, m, off));

    float s = act ? (expf(vx - m) + expf(vy - m)) : 0.0f;
#pragma unroll
    for (int off = 16; off; off >>= 1) s += __shfl_xor_sync(0xFFFFFFFFu, s, off);

    float lse = m + logf(s);
    if (act) {
        float2 o; o.x = vx - lse; o.y = vy - lse;
        ((float2*)(out + (size_t)d * CC))[lane] = o;
    }
}

// ---------------- launch ------------------------------------------------------
extern "C" void kernel_launch(void* const* d_in, const int* in_sizes, int n_in,
                              void* d_out, int out_size) {
    const float* x  = (const float*)d_in[0];
    const void*  ei = d_in[1];                 // int64 OR int32 [2, E] (detected)
    const float* W1 = (const float*)d_in[2];
    const float* b1 = (const float*)d_in[3];
    const float* W2 = (const float*)d_in[4];
    const float* b2 = (const float*)d_in[5];
    float* out = (float*)d_out;

    int n = in_sizes[0] / F;       // 100000
    int E = in_sizes[1] / 2;       // 1600000
    int nb = (n + 1023) / 1024;    // scan blocks (<=128 for n<=131072)

    k_detect<<<1, 32>>>((const int*)ei);
    k_zero<<<(n + 255) / 256, 256>>>(n);
    k_conv<<<(E + 255) / 256, 256>>>(ei, E, n);
    k_scan1<<<nb, 1024>>>(n);
    k_scan2<<<1, 128>>>(nb);
    k_scan3<<<(n + 255) / 256, 256>>>(n);
    k_fill<<<(E + 255) / 256, 256>>>(E);

    k_gemm1  <<<(n + 63) / 64, 256>>>(x, W1, n);
    k_gather1<<<(n * 32 + 255) / 256, 256>>>(b1, n, E);
    k_gemm2  <<<(n + 63) / 64, 320>>>(W2, n);
    k_gather2<<<(n * 32 + 255) / 256, 256>>>(b2, out, n, E);
}

// round 8
// speedup vs baseline: 2.1334x; 1.0906x over previous
#include <cuda_runtime.h>
#include <math.h>

#define F    64      // input / hidden features
#define CC   40      // classes
#define NMAX 100000
#define EMAX 1600000

// ---------------- scratch (device globals: no allocs allowed) ----------------
__device__ int   g_is64;                // 1 if edge_index is int64, 0 if int32
__device__ int   g_cnt [NMAX];          // in-degree (excl self-loop)
__device__ int   g_off [NMAX];          // CSR offsets; post-fill: off[d]=end of row d
__device__ int   g_adj [EMAX];          // dst-grouped source lists
__device__ int   g_bsum[128];           // scan block sums
__device__ int   g_boff[128];           // scanned block offsets
__device__ float g_dinv[NMAX];
__device__ __align__(16) float g_hs [(size_t)NMAX * F];   // dinv-scaled x@W1
__device__ __align__(16) float g_h1 [(size_t)NMAX * F];   // relu(layer-1 out)
__device__ __align__(16) float g_hs2[(size_t)NMAX * CC];  // dinv-scaled h1@W2

// ---------------- dtype detection ----------------
// int64 edges with values in [0, 2^31): every odd 32-bit word is 0.
__global__ void k_detect(const int* __restrict__ ei32) {
    if (threadIdx.x == 0) {
        int all0 = 1;
        for (int i = 1; i < 128; i += 2) all0 &= (ei32[i] == 0);
        g_is64 = all0;
    }
}

// ---------------- CSR build (int atomics only) ----------------
__global__ void k_zero(int n) {
    int i = blockIdx.x * blockDim.x + threadIdx.x;
    if (i < n) g_cnt[i] = 0;
}

// count in-degrees (handles both dtypes)
__global__ void k_conv(const void* __restrict__ ei, int E, int n) {
    int e = blockIdx.x * blockDim.x + threadIdx.x;
    if (e >= E) return;
    int d;
    if (g_is64) d = (int)((const long long*)ei)[(size_t)E + e];
    else        d = ((const int*)ei)[(size_t)E + e];
    d = min(max(d, 0), n - 1);
    atomicAdd(&g_cnt[d], 1);
}

// -------- multi-block exclusive scan of g_cnt -> g_off ------------------------
__global__ void k_scan1(int n) {
    __shared__ int wsum[32];
    int tid = threadIdx.x, lane = tid & 31, wid = tid >> 5;
    int i = blockIdx.x * 1024 + tid;
    int v = (i < n) ? g_cnt[i] : 0;
    int x = v;
#pragma unroll
    for (int off = 1; off < 32; off <<= 1) {
        int t = __shfl_up_sync(0xFFFFFFFFu, x, off);
        if (lane >= off) x += t;
    }
    if (lane == 31) wsum[wid] = x;
    __syncthreads();
    if (wid == 0) {
        int w = wsum[lane];
#pragma unroll
        for (int off = 1; off < 32; off <<= 1) {
            int t = __shfl_up_sync(0xFFFFFFFFu, w, off);
            if (lane >= off) w += t;
        }
        wsum[lane] = w;                 // inclusive scan of warp totals
    }
    __syncthreads();
    int wbase = (wid == 0) ? 0 : wsum[wid - 1];
    if (i < n) {
        g_off[i]  = wbase + x - v;      // block-local exclusive
        g_dinv[i] = rsqrtf((float)(v + 1));   // +1 self-loop
    }
    if (tid == 1023) g_bsum[blockIdx.x] = wbase + x;   // block total
}

__global__ void k_scan2(int nb) {
    __shared__ int wsum[4];
    int tid = threadIdx.x, lane = tid & 31, wid = tid >> 5;
    int v = (tid < nb) ? g_bsum[tid] : 0;
    int x = v;
#pragma unroll
    for (int off = 1; off < 32; off <<= 1) {
        int t = __shfl_up_sync(0xFFFFFFFFu, x, off);
        if (lane >= off) x += t;
    }
    if (lane == 31) wsum[wid] = x;
    __syncthreads();
    if (tid == 0) {
        int c = 0;
#pragma unroll
        for (int w = 0; w < 4; w++) { int t = wsum[w]; wsum[w] = c; c += t; }
    }
    __syncthreads();
    g_boff[tid] = wsum[wid] + x - v;    // exclusive
}

__global__ void k_scan3(int n) {
    int i = blockIdx.x * blockDim.x + threadIdx.x;
    if (i < n) g_off[i] += g_boff[i >> 10];
}

// fill: reads ei directly; atomically advances g_off (post-fill off = row end)
__global__ void k_fill(const void* __restrict__ ei, int E, int n) {
    int e = blockIdx.x * blockDim.x + threadIdx.x;
    if (e >= E) return;
    int s, d;
    if (g_is64) {
        const long long* p = (const long long*)ei;
        s = (int)p[e];
        d = (int)p[(size_t)E + e];
    } else {
        const int* p = (const int*)ei;
        s = p[e];
        d = p[(size_t)E + e];
    }
    s = min(max(s, 0), n - 1);
    d = min(max(d, 0), n - 1);
    int pos = atomicAdd(&g_off[d], 1);
    pos = min(max(pos, 0), E - 1);
    g_adj[pos] = s;
}

// ---------------- GEMM1: g_hs = (x @ W1) * dinv[row] ----------------
__global__ void k_gemm1(const float* __restrict__ x, const float* __restrict__ W, int n) {
    __shared__ float sW[F * F];
    __shared__ float sX[64 * F];
    int tid  = threadIdx.x;
    int row0 = blockIdx.x * 64;

    for (int i = tid; i < F * F; i += 256) sW[i] = W[i];
    for (int i = tid; i < 64 * F; i += 256) {
        int r = row0 + (i >> 6);
        sX[i] = (r < n) ? x[(size_t)r * F + (i & 63)] : 0.0f;
    }
    __syncthreads();

    int col = tid & 63;
    int rg  = tid >> 6;
    float a[16];
#pragma unroll
    for (int j = 0; j < 16; j++) a[j] = 0.0f;

    for (int k = 0; k < F; k++) {
        float w = sW[k * F + col];
#pragma unroll
        for (int j = 0; j < 16; j++)
            a[j] = fmaf(sX[(rg * 16 + j) * F + k], w, a[j]);
    }

#pragma unroll
    for (int j = 0; j < 16; j++) {
        int r = row0 + rg * 16 + j;
        if (r < n) g_hs[(size_t)r * F + col] = a[j] * g_dinv[r];
    }
}

// ------- gather layer 1: 2 dsts/warp, 16 lanes x float4, fused bias+relu -----
__global__ void k_gather1(const float* __restrict__ b1, int n, int E) {
    int gw   = (blockIdx.x * 256 + threadIdx.x) >> 5;
    int lane = threadIdx.x & 31;
    int sub  = lane >> 4;        // 0..1
    int part = lane & 15;        // 0..15 -> float4 slot (64 floats/row)
    int d = gw * 2 + sub;
    if (d >= n) return;

    float4 acc = ((const float4*)(g_hs + (size_t)d * F))[part];  // self-loop
    int end = min(max(g_off[d], 0), E);
    int beg = max(end - g_cnt[d], 0);
    int j = beg;
    for (; j + 4 <= end; j += 4) {
        int s0 = g_adj[j], s1 = g_adj[j+1], s2 = g_adj[j+2], s3 = g_adj[j+3];
        float4 v0 = ((const float4*)(g_hs + (size_t)s0 * F))[part];
        float4 v1 = ((const float4*)(g_hs + (size_t)s1 * F))[part];
        float4 v2 = ((const float4*)(g_hs + (size_t)s2 * F))[part];
        float4 v3 = ((const float4*)(g_hs + (size_t)s3 * F))[part];
        acc.x += (v0.x + v1.x) + (v2.x + v3.x);
        acc.y += (v0.y + v1.y) + (v2.y + v3.y);
        acc.z += (v0.z + v1.z) + (v2.z + v3.z);
        acc.w += (v0.w + v1.w) + (v2.w + v3.w);
    }
    for (; j < end; j++) {
        float4 v = ((const float4*)(g_hs + (size_t)g_adj[j] * F))[part];
        acc.x += v.x; acc.y += v.y; acc.z += v.z; acc.w += v.w;
    }

    float di = g_dinv[d];
    float4 b = ((const float4*)b1)[part];
    float4 o;
    o.x = fmaxf(fmaf(di, acc.x, b.x), 0.0f);
    o.y = fmaxf(fmaf(di, acc.y, b.y), 0.0f);
    o.z = fmaxf(fmaf(di, acc.z, b.z), 0.0f);
    o.w = fmaxf(fmaf(di, acc.w, b.w), 0.0f);
    ((float4*)(g_h1 + (size_t)d * F))[part] = o;
}

// ---------------- GEMM2: g_hs2 = (h1 @ W2) * dinv[row] ----------------
__global__ void k_gemm2(const float* __restrict__ W, int n) {
    __shared__ float sW[F * CC];
    __shared__ float sH[64 * F];
    int tid  = threadIdx.x;            // 320
    int row0 = blockIdx.x * 64;

    for (int i = tid; i < F * CC; i += 320) sW[i] = W[i];
    for (int i = tid; i < 64 * F; i += 320) {
        int r = row0 + (i >> 6);
        sH[i] = (r < n) ? g_h1[(size_t)r * F + (i & 63)] : 0.0f;
    }
    __syncthreads();

    int col = tid % 40;
    int rg  = tid / 40;
    float a[8];
#pragma unroll
    for (int j = 0; j < 8; j++) a[j] = 0.0f;

    for (int k = 0; k < F; k++) {
        float w = sW[k * CC + col];
#pragma unroll
        for (int j = 0; j < 8; j++)
            a[j] = fmaf(sH[(rg * 8 + j) * F + k], w, a[j]);
    }

#pragma unroll
    for (int j = 0; j < 8; j++) {
        int r = row0 + rg * 8 + j;
        if (r < n) g_hs2[(size_t)r * CC + col] = a[j] * g_dinv[r];
    }
}

// ------- gather layer 2: 3 dsts/warp, 10 lanes x float4, fused log_softmax ---
__global__ void k_gather2(const float* __restrict__ b2, float* __restrict__ out,
                          int n, int E) {
    int gw   = (blockIdx.x * 256 + threadIdx.x) >> 5;
    int lane = threadIdx.x & 31;
    int sub  = lane / 10;        // 0..2 (lanes 30,31 -> 3: inactive)
    int part = lane - sub * 10;  // 0..9 -> float4 slot (40 floats/row)
    int d3   = gw * 3 + sub;
    bool act = (sub < 3) && (d3 < n);
    int d    = act ? d3 : 0;

    float4 acc = make_float4(0.0f, 0.0f, 0.0f, 0.0f);
    int beg = 0, end = 0;
    if (act) {
        acc = ((const float4*)(g_hs2 + (size_t)d * CC))[part];  // self-loop
        end = min(max(g_off[d], 0), E);
        beg = max(end - g_cnt[d], 0);
    }
    int j = beg;
    for (; j + 4 <= end; j += 4) {
        int s0 = g_adj[j], s1 = g_adj[j+1], s2 = g_adj[j+2], s3 = g_adj[j+3];
        float4 v0 = ((const float4*)(g_hs2 + (size_t)s0 * CC))[part];
        float4 v1 = ((const float4*)(g_hs2 + (size_t)s1 * CC))[part];
        float4 v2 = ((const float4*)(g_hs2 + (size_t)s2 * CC))[part];
        float4 v3 = ((const float4*)(g_hs2 + (size_t)s3 * CC))[part];
        acc.x += (v0.x + v1.x) + (v2.x + v3.x);
        acc.y += (v0.y + v1.y) + (v2.y + v3.y);
        acc.z += (v0.z + v1.z) + (v2.z + v3.z);
        acc.w += (v0.w + v1.w) + (v2.w + v3.w);
    }
    for (; j < end; j++) {
        float4 v = ((const float4*)(g_hs2 + (size_t)g_adj[j] * CC))[part];
        acc.x += v.x; acc.y += v.y; acc.z += v.z; acc.w += v.w;
    }

    float di = act ? g_dinv[d] : 0.0f;
    float4 b = ((const float4*)b2)[part < 10 ? part : 0];
    float4 v;
    v.x = fmaf(di, acc.x, b.x);
    v.y = fmaf(di, acc.y, b.y);
    v.z = fmaf(di, acc.z, b.z);
    v.w = fmaf(di, acc.w, b.w);
    if (!act) { v.x = v.y = v.z = v.w = -INFINITY; }

    // group (10-lane) max via guarded suffix reduce; result lands at part==0
    float m = fmaxf(fmaxf(v.x, v.y), fmaxf(v.z, v.w));
#pragma unroll
    for (int off = 8; off; off >>= 1) {
        float t = __shfl_sync(0xFFFFFFFFu, m, lane + off);
        if (part + off < 10) m = fmaxf(m, t);
    }
    m = __shfl_sync(0xFFFFFFFFu, m, sub * 10);   // broadcast group max

    float s = act ? (expf(v.x - m) + expf(v.y - m) + expf(v.z - m) + expf(v.w - m))
                  : 0.0f;
#pragma unroll
    for (int off = 8; off; off >>= 1) {
        float t = __shfl_sync(0xFFFFFFFFu, s, lane + off);
        if (part + off < 10) s += t;
    }
    s = __shfl_sync(0xFFFFFFFFu, s, sub * 10);   // broadcast group sum

    if (act) {
        float lse = m + logf(s);
        float4 o;
        o.x = v.x - lse; o.y = v.y - lse; o.z = v.z - lse; o.w = v.w - lse;
        ((float4*)(out + (size_t)d * CC))[part] = o;
    }
}

// ---------------- launch ------------------------------------------------------
extern "C" void kernel_launch(void* const* d_in, const int* in_sizes, int n_in,
                              void* d_out, int out_size) {
    const float* x  = (const float*)d_in[0];
    const void*  ei = d_in[1];                 // int64 OR int32 [2, E] (detected)
    const float* W1 = (const float*)d_in[2];
    const float* b1 = (const float*)d_in[3];
    const float* W2 = (const float*)d_in[4];
    const float* b2 = (const float*)d_in[5];
    float* out = (float*)d_out;

    int n = in_sizes[0] / F;       // 100000
    int E = in_sizes[1] / 2;       // 1600000
    int nb = (n + 1023) / 1024;    // scan blocks (<=128 for n<=131072)

    k_detect<<<1, 32>>>((const int*)ei);
    k_zero<<<(n + 255) / 256, 256>>>(n);
    k_conv<<<(E + 255) / 256, 256>>>(ei, E, n);
    k_scan1<<<nb, 1024>>>(n);
    k_scan2<<<1, 128>>>(nb);
    k_scan3<<<(n + 255) / 256, 256>>>(n);
    k_fill<<<(E + 255) / 256, 256>>>(ei, E, n);

    k_gemm1<<<(n + 63) / 64, 256>>>(x, W1, n);
    int w1 = (n + 1) / 2;                       // warps for gather1
    k_gather1<<<(w1 + 7) / 8, 256>>>(b1, n, E);
    k_gemm2<<<(n + 63) / 64, 320>>>(W2, n);
    int w2 = (n + 2) / 3;                       // warps for gather2
    k_gather2<<<(w2 + 7) / 8, 256>>>(b2, out, n, E);
}

// round 9
// speedup vs baseline: 2.2292x; 1.0449x over previous
#include <cuda_runtime.h>
#include <cuda_fp16.h>
#include <math.h>

#define F    64      // input / hidden features
#define CC   40      // classes
#define NMAX 100000
#define EMAX 1600000

// ---------------- scratch (device globals: no allocs allowed) ----------------
__device__ int   g_is64;                // 1 if edge_index is int64, 0 if int32
__device__ int   g_cnt [NMAX];          // in-degree (excl self-loop)
__device__ int   g_off [NMAX];          // CSR offsets; post-fill: off[d]=end of row d
__device__ int   g_adj [EMAX];          // dst-grouped source lists
__device__ int   g_bsum[128];           // scan block sums
__device__ int   g_boff[128];           // scanned block offsets
__device__ float g_dinv[NMAX];
__device__ __align__(16) __half g_hs [(size_t)NMAX * F];  // fp16 dinv-scaled x@W1
__device__ __align__(16) float  g_h1 [(size_t)NMAX * F];  // relu(layer-1 out), fp32
__device__ __align__(16) float  g_hs2[(size_t)NMAX * CC]; // dinv-scaled h1@W2, fp32

// ---------------- init: detect dtype (warp 0) + zero counts ------------------
// int64 edges with values in [0, 2^31): every odd 32-bit word is 0.
__global__ void k_init(const int* __restrict__ ei32, int n) {
    if (blockIdx.x == 0 && threadIdx.x < 32) {
        int w = ei32[1 + 2 * threadIdx.x];           // odd words 1,3,...,63
        unsigned nz = __ballot_sync(0xFFFFFFFFu, w != 0);
        if (threadIdx.x == 0) g_is64 = (nz == 0u);
    }
    int i = blockIdx.x * blockDim.x + threadIdx.x;
    if (i < n) g_cnt[i] = 0;
}

// ---------------- count in-degrees (4 edges/thread, int atomics) -------------
__global__ void k_conv(const void* __restrict__ ei, int E, int n) {
    int e0 = (blockIdx.x * blockDim.x + threadIdx.x) * 4;
    if (e0 >= E) return;
    if (g_is64) {
        const long long* p = (const long long*)ei;
        for (int k = 0; k < 4 && e0 + k < E; k++) {
            int d = (int)p[(size_t)E + e0 + k];
            atomicAdd(&g_cnt[min(max(d, 0), n - 1)], 1);
        }
    } else {
        const int* p = (const int*)ei + (size_t)E;
        if (e0 + 3 < E) {
            int4 d4 = *(const int4*)(p + e0);        // E multiple of 4 in practice
            atomicAdd(&g_cnt[min(max(d4.x, 0), n - 1)], 1);
            atomicAdd(&g_cnt[min(max(d4.y, 0), n - 1)], 1);
            atomicAdd(&g_cnt[min(max(d4.z, 0), n - 1)], 1);
            atomicAdd(&g_cnt[min(max(d4.w, 0), n - 1)], 1);
        } else {
            for (int k = 0; k < 4 && e0 + k < E; k++)
                atomicAdd(&g_cnt[min(max(p[e0 + k], 0), n - 1)], 1);
        }
    }
}

// -------- multi-block exclusive scan of g_cnt -> g_off ------------------------
__global__ void k_scan1(int n) {
    __shared__ int wsum[32];
    int tid = threadIdx.x, lane = tid & 31, wid = tid >> 5;
    int i = blockIdx.x * 1024 + tid;
    int v = (i < n) ? g_cnt[i] : 0;
    int x = v;
#pragma unroll
    for (int off = 1; off < 32; off <<= 1) {
        int t = __shfl_up_sync(0xFFFFFFFFu, x, off);
        if (lane >= off) x += t;
    }
    if (lane == 31) wsum[wid] = x;
    __syncthreads();
    if (wid == 0) {
        int w = wsum[lane];
#pragma unroll
        for (int off = 1; off < 32; off <<= 1) {
            int t = __shfl_up_sync(0xFFFFFFFFu, w, off);
            if (lane >= off) w += t;
        }
        wsum[lane] = w;                 // inclusive scan of warp totals
    }
    __syncthreads();
    int wbase = (wid == 0) ? 0 : wsum[wid - 1];
    if (i < n) {
        g_off[i]  = wbase + x - v;      // block-local exclusive
        g_dinv[i] = rsqrtf((float)(v + 1));   // +1 self-loop
    }
    if (tid == 1023) g_bsum[blockIdx.x] = wbase + x;   // block total
}

__global__ void k_scan2(int nb) {
    __shared__ int wsum[4];
    int tid = threadIdx.x, lane = tid & 31, wid = tid >> 5;
    int v = (tid < nb) ? g_bsum[tid] : 0;
    int x = v;
#pragma unroll
    for (int off = 1; off < 32; off <<= 1) {
        int t = __shfl_up_sync(0xFFFFFFFFu, x, off);
        if (lane >= off) x += t;
    }
    if (lane == 31) wsum[wid] = x;
    __syncthreads();
    if (tid == 0) {
        int c = 0;
#pragma unroll
        for (int w = 0; w < 4; w++) { int t = wsum[w]; wsum[w] = c; c += t; }
    }
    __syncthreads();
    g_boff[tid] = wsum[wid] + x - v;    // exclusive
}

__global__ void k_scan3(int n) {
    int i = blockIdx.x * blockDim.x + threadIdx.x;
    if (i < n) g_off[i] += g_boff[i >> 10];
}

// fill: atomically advances g_off (post-fill off[d] = end of row d)
__global__ void k_fill(const void* __restrict__ ei, int E, int n) {
    int e = blockIdx.x * blockDim.x + threadIdx.x;
    if (e >= E) return;
    int s, d;
    if (g_is64) {
        const long long* p = (const long long*)ei;
        s = (int)p[e];
        d = (int)p[(size_t)E + e];
    } else {
        const int* p = (const int*)ei;
        s = p[e];
        d = p[(size_t)E + e];
    }
    s = min(max(s, 0), n - 1);
    d = min(max(d, 0), n - 1);
    int pos = atomicAdd(&g_off[d], 1);
    pos = min(max(pos, 0), E - 1);
    g_adj[pos] = s;
}

// -------- GEMM1: g_hs = fp16( (x @ W1) * dinv[row] ) -------------------------
__global__ void k_gemm1(const float* __restrict__ x, const float* __restrict__ W, int n) {
    __shared__ float sW[F * F];
    __shared__ float sX[64 * F];
    int tid  = threadIdx.x;
    int row0 = blockIdx.x * 64;

    for (int i = tid; i < F * F; i += 256) sW[i] = W[i];
    for (int i = tid; i < 64 * F; i += 256) {
        int r = row0 + (i >> 6);
        sX[i] = (r < n) ? x[(size_t)r * F + (i & 63)] : 0.0f;
    }
    __syncthreads();

    int col = tid & 63;
    int rg  = tid >> 6;
    float a[16];
#pragma unroll
    for (int j = 0; j < 16; j++) a[j] = 0.0f;

    for (int k = 0; k < F; k++) {
        float w = sW[k * F + col];
#pragma unroll
        for (int j = 0; j < 16; j++)
            a[j] = fmaf(sX[(rg * 16 + j) * F + k], w, a[j]);
    }

#pragma unroll
    for (int j = 0; j < 16; j++) {
        int r = row0 + rg * 16 + j;
        if (r < n) g_hs[(size_t)r * F + col] = __float2half_rn(a[j] * g_dinv[r]);
    }
}

// ------- gather layer 1: 2 dsts/warp, 16 lanes x 4 halves (uint2) ------------
__device__ __forceinline__ void acc_half4(float4& a, uint2 u) {
    float2 lo = __half22float2(*(const __half2*)&u.x);
    float2 hi = __half22float2(*(const __half2*)&u.y);
    a.x += lo.x; a.y += lo.y; a.z += hi.x; a.w += hi.y;
}

__global__ void k_gather1(const float* __restrict__ b1, int n, int E) {
    int gw   = (blockIdx.x * 256 + threadIdx.x) >> 5;
    int lane = threadIdx.x & 31;
    int sub  = lane >> 4;        // 0..1
    int part = lane & 15;        // 0..15 -> 4-half slot (64 halves/row)
    int d = gw * 2 + sub;
    if (d >= n) return;

    float4 acc = make_float4(0.0f, 0.0f, 0.0f, 0.0f);
    acc_half4(acc, ((const uint2*)(g_hs + (size_t)d * F))[part]);   // self-loop
    int end = min(max(g_off[d], 0), E);
    int beg = max(end - g_cnt[d], 0);
    int j = beg;
    for (; j + 8 <= end; j += 8) {
        uint2 v[8];
#pragma unroll
        for (int k = 0; k < 8; k++)
            v[k] = ((const uint2*)(g_hs + (size_t)g_adj[j + k] * F))[part];
#pragma unroll
        for (int k = 0; k < 8; k++) acc_half4(acc, v[k]);
    }
    if (j + 4 <= end) {
        uint2 v[4];
#pragma unroll
        for (int k = 0; k < 4; k++)
            v[k] = ((const uint2*)(g_hs + (size_t)g_adj[j + k] * F))[part];
#pragma unroll
        for (int k = 0; k < 4; k++) acc_half4(acc, v[k]);
        j += 4;
    }
    for (; j < end; j++)
        acc_half4(acc, ((const uint2*)(g_hs + (size_t)g_adj[j] * F))[part]);

    float di = g_dinv[d];
    float4 b = ((const float4*)b1)[part];
    float4 o;
    o.x = fmaxf(fmaf(di, acc.x, b.x), 0.0f);
    o.y = fmaxf(fmaf(di, acc.y, b.y), 0.0f);
    o.z = fmaxf(fmaf(di, acc.z, b.z), 0.0f);
    o.w = fmaxf(fmaf(di, acc.w, b.w), 0.0f);
    ((float4*)(g_h1 + (size_t)d * F))[part] = o;
}

// ---------------- GEMM2: g_hs2 = (h1 @ W2) * dinv[row] ----------------
__global__ void k_gemm2(const float* __restrict__ W, int n) {
    __shared__ float sW[F * CC];
    __shared__ float sH[64 * F];
    int tid  = threadIdx.x;            // 320
    int row0 = blockIdx.x * 64;

    for (int i = tid; i < F * CC; i += 320) sW[i] = W[i];
    for (int i = tid; i < 64 * F; i += 320) {
        int r = row0 + (i >> 6);
        sH[i] = (r < n) ? g_h1[(size_t)r * F + (i & 63)] : 0.0f;
    }
    __syncthreads();

    int col = tid % 40;
    int rg  = tid / 40;
    float a[8];
#pragma unroll
    for (int j = 0; j < 8; j++) a[j] = 0.0f;

    for (int k = 0; k < F; k++) {
        float w = sW[k * CC + col];
#pragma unroll
        for (int j = 0; j < 8; j++)
            a[j] = fmaf(sH[(rg * 8 + j) * F + k], w, a[j]);
    }

#pragma unroll
    for (int j = 0; j < 8; j++) {
        int r = row0 + rg * 8 + j;
        if (r < n) g_hs2[(size_t)r * CC + col] = a[j] * g_dinv[r];
    }
}

// ------- gather layer 2: 3 dsts/warp, 10 lanes x float4, fused log_softmax ---
__global__ void k_gather2(const float* __restrict__ b2, float* __restrict__ out,
                          int n, int E) {
    int gw   = (blockIdx.x * 256 + threadIdx.x) >> 5;
    int lane = threadIdx.x & 31;
    int sub  = lane / 10;        // 0..2 (lanes 30,31 -> 3: inactive)
    int part = lane - sub * 10;  // 0..9 -> float4 slot (40 floats/row)
    int d3   = gw * 3 + sub;
    bool act = (sub < 3) && (d3 < n);
    int d    = act ? d3 : 0;

    float4 acc = make_float4(0.0f, 0.0f, 0.0f, 0.0f);
    int beg = 0, end = 0;
    if (act) {
        acc = ((const float4*)(g_hs2 + (size_t)d * CC))[part];  // self-loop
        end = min(max(g_off[d], 0), E);
        beg = max(end - g_cnt[d], 0);
    }
    int j = beg;
    for (; j + 4 <= end; j += 4) {
        int s0 = g_adj[j], s1 = g_adj[j+1], s2 = g_adj[j+2], s3 = g_adj[j+3];
        float4 v0 = ((const float4*)(g_hs2 + (size_t)s0 * CC))[part];
        float4 v1 = ((const float4*)(g_hs2 + (size_t)s1 * CC))[part];
        float4 v2 = ((const float4*)(g_hs2 + (size_t)s2 * CC))[part];
        float4 v3 = ((const float4*)(g_hs2 + (size_t)s3 * CC))[part];
        acc.x += (v0.x + v1.x) + (v2.x + v3.x);
        acc.y += (v0.y + v1.y) + (v2.y + v3.y);
        acc.z += (v0.z + v1.z) + (v2.z + v3.z);
        acc.w += (v0.w + v1.w) + (v2.w + v3.w);
    }
    for (; j < end; j++) {
        float4 v = ((const float4*)(g_hs2 + (size_t)g_adj[j] * CC))[part];
        acc.x += v.x; acc.y += v.y; acc.z += v.z; acc.w += v.w;
    }

    float di = act ? g_dinv[d] : 0.0f;
    float4 b = ((const float4*)b2)[part < 10 ? part : 0];
    float4 v;
    v.x = fmaf(di, acc.x, b.x);
    v.y = fmaf(di, acc.y, b.y);
    v.z = fmaf(di, acc.z, b.z);
    v.w = fmaf(di, acc.w, b.w);
    if (!act) { v.x = v.y = v.z = v.w = -INFINITY; }

    // group (10-lane) max via guarded suffix reduce
    float m = fmaxf(fmaxf(v.x, v.y), fmaxf(v.z, v.w));
#pragma unroll
    for (int off = 8; off; off >>= 1) {
        float t = __shfl_sync(0xFFFFFFFFu, m, lane + off);
        if (part + off < 10) m = fmaxf(m, t);
    }
    m = __shfl_sync(0xFFFFFFFFu, m, sub * 10);   // broadcast group max

    float s = act ? (expf(v.x - m) + expf(v.y - m) + expf(v.z - m) + expf(v.w - m))
                  : 0.0f;
#pragma unroll
    for (int off = 8; off; off >>= 1) {
        float t = __shfl_sync(0xFFFFFFFFu, s, lane + off);
        if (part + off < 10) s += t;
    }
    s = __shfl_sync(0xFFFFFFFFu, s, sub * 10);   // broadcast group sum

    if (act) {
        float lse = m + logf(s);
        float4 o;
        o.x = v.x - lse; o.y = v.y - lse; o.z = v.z - lse; o.w = v.w - lse;
        ((float4*)(out + (size_t)d * CC))[part] = o;
    }
}

// ---------------- launch ------------------------------------------------------
extern "C" void kernel_launch(void* const* d_in, const int* in_sizes, int n_in,
                              void* d_out, int out_size) {
    const float* x  = (const float*)d_in[0];
    const void*  ei = d_in[1];                 // int64 OR int32 [2, E] (detected)
    const float* W1 = (const float*)d_in[2];
    const float* b1 = (const float*)d_in[3];
    const float* W2 = (const float*)d_in[4];
    const float* b2 = (const float*)d_in[5];
    float* out = (float*)d_out;

    int n = in_sizes[0] / F;       // 100000
    int E = in_sizes[1] / 2;       // 1600000
    int nb = (n + 1023) / 1024;    // scan blocks (<=128 for n<=131072)

    k_init<<<(n + 255) / 256, 256>>>((const int*)ei, n);
    k_conv<<<(E / 4 + 255) / 256, 256>>>(ei, E, n);
    k_scan1<<<nb, 1024>>>(n);
    k_scan2<<<1, 128>>>(nb);
    k_scan3<<<(n + 255) / 256, 256>>>(n);
    k_fill<<<(E + 255) / 256, 256>>>(ei, E, n);

    k_gemm1<<<(n + 63) / 64, 256>>>(x, W1, n);
    int w1 = (n + 1) / 2;                       // warps for gather1
    k_gather1<<<(w1 + 7) / 8, 256>>>(b1, n, E);
    k_gemm2<<<(n + 63) / 64, 320>>>(W2, n);
    int w2 = (n + 2) / 3;                       // warps for gather2
    k_gather2<<<(w2 + 7) / 8, 256>>>(b2, out, n, E);
}